// round 9
// baseline (speedup 1.0000x reference)
#include <cuda_runtime.h>
#include <cuda_fp16.h>
#include <cstdint>

#define E_   8
#define CAP_ 2048
#define D_   1024
#define H_   4096

// ---------------- scratch (device globals; no runtime allocation) ----------------
__device__ __half g_Xh [(size_t)E_ * CAP_ * D_];   // [E*2048][1024]
__device__ __half g_W1h[(size_t)E_ * H_   * D_];   // [E*4096][1024]
__device__ __half g_W2T[(size_t)E_ * D_   * H_];   // [E*1024][4096]  (W2^T)
__device__ __half g_Y  [(size_t)E_ * CAP_ * H_];   // [E*2048][4096]

// ---------------- PTX helpers (portable: sm_80+ features only) ----------------
__device__ __forceinline__ uint32_t smem_u32(const void* p) {
    uint32_t a;
    asm("{ .reg .u64 t; cvta.to.shared.u64 t, %1; cvt.u32.u64 %0, t; }" : "=r"(a) : "l"(p));
    return a;
}
__device__ __forceinline__ void cpa16(uint32_t s, const void* g) {
    asm volatile("cp.async.cg.shared.global [%0], [%1], 16;" :: "r"(s), "l"(g) : "memory");
}
__device__ __forceinline__ void ldsm4(uint32_t r[4], uint32_t addr) {
    asm volatile("ldmatrix.sync.aligned.m8n8.x4.shared.b16 {%0,%1,%2,%3}, [%4];"
                 : "=r"(r[0]), "=r"(r[1]), "=r"(r[2]), "=r"(r[3]) : "r"(addr));
}
__device__ __forceinline__ void mma16816(float d[4], const uint32_t a[4],
                                         uint32_t b0, uint32_t b1) {
    asm volatile("mma.sync.aligned.m16n8k16.row.col.f32.f16.f16.f32 "
                 "{%0,%1,%2,%3},{%4,%5,%6,%7},{%8,%9},{%0,%1,%2,%3};"
                 : "+f"(d[0]), "+f"(d[1]), "+f"(d[2]), "+f"(d[3])
                 : "r"(a[0]), "r"(a[1]), "r"(a[2]), "r"(a[3]), "r"(b0), "r"(b1));
}
__device__ __forceinline__ uint32_t h2u(__half2 h) {
    return *reinterpret_cast<uint32_t*>(&h);
}

// ---------------- convert: fp32 -> fp16 elementwise; dst chosen in DEVICE code ----------------
template<int TGT>   // 0 -> g_Xh, 1 -> g_W1h
__global__ void conv_f16(const float* __restrict__ src) {
    __half* dst = (TGT == 0) ? g_Xh : g_W1h;
    size_t t = (size_t)blockIdx.x * 256 + threadIdx.x;   // one float4 per thread
    float4 v = *((const float4*)src + t);
    __half2 h0 = __floats2half2_rn(v.x, v.y);
    __half2 h1 = __floats2half2_rn(v.z, v.w);
    *(uint2*)(dst + t * 4) = make_uint2(h2u(h0), h2u(h1));
}

// ---------------- W2 transpose + convert: [E,H,D] fp32 -> [E,D][H] fp16 ----------------
__global__ void conv_w2t(const float* __restrict__ w2) {
    __shared__ float tile[32][33];
    int e  = blockIdx.z;
    int d0 = blockIdx.x * 32;
    int h0 = blockIdx.y * 32;
    int tx = threadIdx.x, ty = threadIdx.y;
#pragma unroll
    for (int r = 0; r < 4; r++) {
        int h = h0 + ty + r * 8;
        tile[ty + r * 8][tx] = w2[((size_t)(e * H_ + h)) * D_ + d0 + tx];
    }
    __syncthreads();
#pragma unroll
    for (int r = 0; r < 4; r++) {
        int d = d0 + ty + r * 8;
        int h = h0 + tx;
        g_W2T[((size_t)(e * D_ + d)) * H_ + h] = __float2half_rn(tile[tx][ty + r * 8]);
    }
}

// ---------------- fp16 GEMM, mma.sync + cp.async, register-fragment double buffering ----
// 128x128 CTA tile, 4 warps (2x2) of 64x64 warp tiles, 128 threads,
// 3 stages (96 KB smem) -> 2 CTAs/SM.
#define TM 128
#define TN 128
#define WM 64
#define WN 64
#define NSTAGE 3
#define STB ((TM + TN) * 128)              // 32 KB per stage
#define SMEM_TOT (NSTAGE * STB)            // 96 KB

template<int PHASE>
__global__ void __launch_bounds__(128, 2) gemm_mma(const float* __restrict__ bias,
                                                   float* __restrict__ outF) {
    constexpr int Ntot = (PHASE == 1) ? H_ : D_;
    constexpr int KSEG = (PHASE == 1) ? D_ : H_;
    constexpr int NCH  = KSEG / 64;        // 64-wide K chunks
    constexpr int Mt   = CAP_ / TM;
    constexpr int Nt   = Ntot / TN;
    constexpr int WROWS = WM / 16, WCOLS = WN / 8, BT16 = WN / 16;

    extern __shared__ char smem[];
    const uint32_t sb = smem_u32(smem);
    const int tid = threadIdx.x, wid = tid >> 5, lane = tid & 31;

    const int idx = blockIdx.x;
    const int mt = idx % Mt;
    const int nt = (idx / Mt) % Nt;
    const int e  = idx / (Mt * Nt);
    const int m0 = mt * TM, n0 = nt * TN;

    const __half* A = (PHASE == 1) ? g_Xh  : g_Y;
    const __half* B = (PHASE == 1) ? g_W1h : g_W2T;
    const __half* Ab = A + (size_t)(e * CAP_ + m0) * KSEG;
    const __half* Bb = B + (size_t)(e * Ntot + n0) * KSEG;

    // Loader: one thread covers rows {tid>>3, +16, +32, ...}, 16B chunk (tid&7).
    // Row step 16 keeps (row & 7) constant -> swizzle XOR constant -> smem addr
    // advances by exactly 16*128 = 2048 bytes per step. Register-lean.
    const int lrow = tid >> 3, lc16 = tid & 7;
    const uint32_t lsw = ((lc16 ^ (lrow & 7)) << 4) + lrow * 128;
    auto issue = [&](int c) {
        const int k0 = c * 64;
        const uint32_t s = sb + (c % NSTAGE) * STB;
        const __half* gA = Ab + (size_t)lrow * KSEG + k0 + lc16 * 8;
        uint32_t sa = s + lsw;
#pragma unroll 1
        for (int t = 0; t < TM / 16; ++t) {
            cpa16(sa, gA);
            sa += 16 * 128;
            gA += (size_t)16 * KSEG;
        }
        const __half* gB = Bb + (size_t)lrow * KSEG + k0 + lc16 * 8;
        uint32_t sbm = s + TM * 128 + lsw;
#pragma unroll 1
        for (int t = 0; t < TN / 16; ++t) {
            cpa16(sbm, gB);
            sbm += 16 * 128;
            gB += (size_t)16 * KSEG;
        }
        asm volatile("cp.async.commit_group;" ::: "memory");
    };

    const int m_off = (wid >> 1) * WM;     // 2x2 warp grid
    const int n_off = (wid & 1) * WN;

    float acc[WROWS][WCOLS][4] = {};
    uint32_t aF[2][WROWS][4], bF[2][BT16][4];

    // fragment loads for k16-step kk of the chunk resident in stage starting at sA
    auto ldfrags = [&](int b, uint32_t sA, int kk) {
        const uint32_t sB = sA + TM * 128;
#pragma unroll
        for (int i = 0; i < WROWS; ++i) {
            int row = m_off + 16 * i + (lane & 15);
            int ch  = kk * 2 + (lane >> 4);
            ldsm4(aF[b][i], sA + row * 128 + ((ch ^ (row & 7)) << 4));
        }
#pragma unroll
        for (int j4 = 0; j4 < BT16; ++j4) {
            int row = n_off + 16 * j4 + ((lane >> 4) << 3) + (lane & 7);
            int ch  = kk * 2 + ((lane >> 3) & 1);
            ldsm4(bF[b][j4], sB + row * 128 + ((ch ^ (row & 7)) << 4));
        }
    };
    auto mmas = [&](int b) {
#pragma unroll
        for (int i = 0; i < WROWS; ++i)
#pragma unroll
            for (int j = 0; j < WCOLS; ++j)
                mma16816(acc[i][j], aF[b][i],
                         bF[b][j >> 1][(j & 1) * 2], bF[b][j >> 1][(j & 1) * 2 + 1]);
    };

    // ---- prologue: 2 stages in flight, stage 0 resident, frags(0, kk=0) in buf 0 ----
    issue(0);
    issue(1);
    asm volatile("cp.async.wait_group 1;" ::: "memory");
    __syncthreads();
    ldfrags(0, sb, 0);

    int buf = 0;
    for (int c = 0; c < NCH; ++c) {
        const uint32_t sA  = sb + (c % NSTAGE) * STB;
        const uint32_t sA1 = sb + ((c + 1) % NSTAGE) * STB;
#pragma unroll
        for (int kk = 0; kk < 3; ++kk) {   // prefetch kk+1 frags, then mma kk
            ldfrags(buf ^ 1, sA, kk + 1);
            mmas(buf);
            buf ^= 1;
        }
        // stage-boundary: commit next loads, make stage c+1 resident, prefetch its
        // kk=0 frags, and overlap all of that with the last mma of chunk c.
        if (c + 2 < NCH) issue(c + 2);
        else asm volatile("cp.async.commit_group;" ::: "memory");
        asm volatile("cp.async.wait_group 1;" ::: "memory");
        __syncthreads();
        if (c + 1 < NCH) ldfrags(buf ^ 1, sA1, 0);
        mmas(buf);
        buf ^= 1;
    }

    // ---- epilogue ----
    const int r_lane = lane >> 2;
    const int c_lane = (lane & 3) * 2;
    const float* brow = bias + (size_t)e * Ntot;
#pragma unroll
    for (int i = 0; i < WROWS; ++i) {
#pragma unroll
        for (int half = 0; half < 2; ++half) {
            const int m = m0 + m_off + 16 * i + r_lane + half * 8;
            if (PHASE == 1) {
                __half* yrow = g_Y + (size_t)(e * CAP_ + m) * H_;
#pragma unroll
                for (int j = 0; j < WCOLS; ++j) {
                    const int col = n0 + n_off + 8 * j + c_lane;
                    float v0 = acc[i][j][half * 2 + 0] + brow[col];
                    float v1 = acc[i][j][half * 2 + 1] + brow[col + 1];
                    v0 = fmaxf(v0, 0.f);
                    v1 = fmaxf(v1, 0.f);
                    *(uint32_t*)(yrow + col) = h2u(__floats2half2_rn(v0, v1));
                }
            } else {
                float* orow = outF + (size_t)(e * CAP_ + m) * D_;
#pragma unroll
                for (int j = 0; j < WCOLS; ++j) {
                    const int col = n0 + n_off + 8 * j + c_lane;
                    float2 f;
                    f.x = acc[i][j][half * 2 + 0] + brow[col];
                    f.y = acc[i][j][half * 2 + 1] + brow[col + 1];
                    *(float2*)(orow + col) = f;
                }
            }
        }
    }
}

// ---------------- launch ----------------
extern "C" void kernel_launch(void* const* d_in, const int* in_sizes, int n_in,
                              void* d_out, int out_size) {
    const float* x  = (const float*)d_in[0];   // [E, CAP, D]
    const float* w1 = (const float*)d_in[1];   // [E, H, D]
    const float* b1 = (const float*)d_in[2];   // [E, H]
    const float* w2 = (const float*)d_in[3];   // [E, H, D]
    const float* b2 = (const float*)d_in[4];   // [E, D]
    float* out = (float*)d_out;                // [E, CAP, D]

    cudaFuncSetAttribute(gemm_mma<1>, cudaFuncAttributeMaxDynamicSharedMemorySize, SMEM_TOT);
    cudaFuncSetAttribute(gemm_mma<2>, cudaFuncAttributeMaxDynamicSharedMemorySize, SMEM_TOT);

    // 1) conversions (destinations resolved in device code)
    conv_f16<0><<<(E_ * CAP_ * D_ / 4) / 256, 256>>>(x);           // X  -> g_Xh
    conv_f16<1><<<(E_ * H_   * D_ / 4) / 256, 256>>>(w1);          // W1 -> g_W1h
    conv_w2t<<<dim3(D_ / 32, H_ / 32, E_), dim3(32, 8)>>>(w2);     // W2 -> g_W2T (transposed)

    // 2) GEMM1: relu(X W1^T + b1) -> g_Y (fp16)
    gemm_mma<1><<<(CAP_ / TM) * (H_ / TN) * E_, 128, SMEM_TOT>>>(b1, nullptr);

    // 3) GEMM2: Y W2 + b2 -> out (fp32)
    gemm_mma<2><<<(CAP_ / TM) * (D_ / TN) * E_, 128, SMEM_TOT>>>(b2, out);
}